// round 7
// baseline (speedup 1.0000x reference)
#include <cuda_runtime.h>
#include <math.h>
#include <stdint.h>

// Problem constants
#define BB   4096
#define LATD 128
#define HD   512
#define IND  16
#define TT   32
#define MLPD 512
#define KP   544   // 512 (h) + 16 (x) + 16 zero pad -> 17 * 32

// ---------------------------------------------------------------------------
// Scratch (static device globals; no runtime allocation allowed)
// ---------------------------------------------------------------------------
__device__ float g_bufA[BB * MLPD];
__device__ float g_bufB[BB * MLPD];
__device__ float g_hx[2][BB * KP];      // concat [h(512) | x(16) | pad(16)]
__device__ float g_c[BB * HD];
__device__ float g_Wcat[4 * HD * KP];   // permuted [2048, 544]
__device__ float g_biasr[4 * HD];       // permuted bih+bhh

__device__ __forceinline__ float sigf(float x) { return 1.0f / (1.0f + expf(-x)); }

// ---------------------------------------------------------------------------
// tf32 helpers
// ---------------------------------------------------------------------------
__device__ __forceinline__ void split_tf32(float v, uint32_t& hi, uint32_t& lo) {
    asm("cvt.rna.tf32.f32 %0, %1;" : "=r"(hi) : "f"(v));
    float r = v - __uint_as_float(hi);
    asm("cvt.rna.tf32.f32 %0, %1;" : "=r"(lo) : "f"(r));
}
__device__ __forceinline__ void mma_tf32(float* c, const uint32_t* a, const uint32_t* b) {
    asm volatile(
        "mma.sync.aligned.m16n8k8.row.col.f32.tf32.tf32.f32 "
        "{%0,%1,%2,%3}, {%4,%5,%6,%7}, {%8,%9}, {%0,%1,%2,%3};"
        : "+f"(c[0]), "+f"(c[1]), "+f"(c[2]), "+f"(c[3])
        : "r"(a[0]), "r"(a[1]), "r"(a[2]), "r"(a[3]), "r"(b[0]), "r"(b[1]));
}

#define SS 36   // smem row stride in floats (conflict-free fragment loads)

// ---------------------------------------------------------------------------
// Shared mainloop (3xTF32): acc[2][8][4] += A[bm:bm+128,:K] @ W[bn:bn+128,:K]^T
// A, W fp32 row-major (ld in floats). 256 threads = 8 warps, warp tile 32x64.
// K % 32 == 0. smem: sA[128][36], sW[128][36].
// ---------------------------------------------------------------------------
__device__ __forceinline__ void run_mainloop(
    float acc[2][8][4],
    const float* __restrict__ A, int lda,
    const float* __restrict__ W, int ldw,
    int K, int bm, int bn, float* smem)
{
    const int tid = threadIdx.x;
    const int wid = tid >> 5, lane = tid & 31;
    const int wm = wid >> 1, wn = wid & 1;
    const int g = lane >> 2, tig = lane & 3;

    float* sA = smem;
    float* sW = smem + 128 * SS;

    for (int k0 = 0; k0 < K; k0 += 32) {
#pragma unroll
        for (int p = 0; p < 4; p++) {
            const int lin = p * 1024 + tid * 4;
            const int r = lin >> 5, c = lin & 31;
            *(float4*)&sA[r * SS + c] = *(const float4*)&A[(size_t)(bm + r) * lda + k0 + c];
            *(float4*)&sW[r * SS + c] = *(const float4*)&W[(size_t)(bn + r) * ldw + k0 + c];
        }
        __syncthreads();

#pragma unroll
        for (int kk = 0; kk < 4; kk++) {
            const int kc = kk * 8 + tig;
            uint32_t aH[2][4], aL[2][4];
#pragma unroll
            for (int m = 0; m < 2; m++) {
                const int row = wm * 32 + m * 16 + g;
                split_tf32(sA[row * SS + kc],           aH[m][0], aL[m][0]);
                split_tf32(sA[(row + 8) * SS + kc],     aH[m][1], aL[m][1]);
                split_tf32(sA[row * SS + kc + 4],       aH[m][2], aL[m][2]);
                split_tf32(sA[(row + 8) * SS + kc + 4], aH[m][3], aL[m][3]);
            }
#pragma unroll
            for (int j = 0; j < 8; j++) {
                const int nrow = wn * 64 + j * 8 + g;
                uint32_t bH[2], bL[2];
                split_tf32(sW[nrow * SS + kc],     bH[0], bL[0]);
                split_tf32(sW[nrow * SS + kc + 4], bH[1], bL[1]);
#pragma unroll
                for (int m = 0; m < 2; m++) {
                    mma_tf32(acc[m][j], aH[m], bH);
                    mma_tf32(acc[m][j], aL[m], bH);
                    mma_tf32(acc[m][j], aH[m], bL);
                }
            }
        }
        __syncthreads();
    }
}

// ---------------------------------------------------------------------------
// GEMM: C[.,col] = act(A @ W^T + bias), fp32 out with row stride ldc.
// ACT: 0 none, 1 LeakyReLU(0.2). Grid: (N/128, M/128).
// ---------------------------------------------------------------------------
template <int ACT>
__global__ __launch_bounds__(256)
void gemm_mma(const float* __restrict__ A, int lda,
              const float* __restrict__ W, int ldw,
              const float* __restrict__ bias, int K,
              float* __restrict__ C, int ldc)
{
    __shared__ __align__(16) float smem[2 * 128 * SS];
    float acc[2][8][4] = {};
    const int bm = blockIdx.y * 128, bn = blockIdx.x * 128;

    run_mainloop(acc, A, lda, W, ldw, K, bm, bn, smem);

    const int wid = threadIdx.x >> 5, lane = threadIdx.x & 31;
    const int wm = wid >> 1, wn = wid & 1;

#pragma unroll
    for (int m = 0; m < 2; m++)
#pragma unroll
        for (int j = 0; j < 8; j++) {
            const int col = bn + wn * 64 + j * 8 + (lane & 3) * 2;
            const int row0 = bm + wm * 32 + m * 16 + (lane >> 2);
#pragma unroll
            for (int rp = 0; rp < 2; rp++) {
                const int r = row0 + rp * 8;
                float v0 = acc[m][j][rp * 2 + 0] + bias[col];
                float v1 = acc[m][j][rp * 2 + 1] + bias[col + 1];
                if (ACT == 1) {
                    v0 = (v0 >= 0.0f) ? v0 : 0.2f * v0;
                    v1 = (v1 >= 0.0f) ? v1 : 0.2f * v1;
                }
                *(float2*)&C[(size_t)r * ldc + col] = make_float2(v0, v1);
            }
        }
}

// ---------------------------------------------------------------------------
// LSTM fused gate kernel. A = [h|x|0] fp32 [B,544]; W = permuted [2048,544].
// CTA (nb, mb): rows mb*128, block-local cols: 0-31=i, 32-63=f, 64-95=g, 96-127=o
// for hcols nb*32..+31. Epilogue: g/o exchanged via smem, gate math, c updated
// in place, h written fp32 into next Acat buffer (cols 0..511, ld 544).
// ---------------------------------------------------------------------------
__global__ __launch_bounds__(256)
void lstm_mma_kernel(const float* __restrict__ Ain,
                     const float* __restrict__ W,
                     const float* __restrict__ bias_r,
                     float* __restrict__ cst,
                     float* __restrict__ Aout)
{
    __shared__ __align__(16) float smem[2 * 128 * SS];   // >= 128*66 floats
    float acc[2][8][4] = {};
    const int bm = blockIdx.y * 128, bn = blockIdx.x * 128;

    run_mainloop(acc, Ain, KP, W, KP, KP, bm, bn, smem);

    const int wid = threadIdx.x >> 5, lane = threadIdx.x & 31;
    const int wm = wid >> 1, wn = wid & 1;
    float* stage = smem;   // [128][66]

    if (wn == 1) {
#pragma unroll
        for (int m = 0; m < 2; m++)
#pragma unroll
            for (int j = 0; j < 8; j++)
#pragma unroll
                for (int rp = 0; rp < 2; rp++) {
                    const int rl = wm * 32 + m * 16 + (lane >> 2) + rp * 8;
                    const int cl = j * 8 + (lane & 3) * 2;
                    *(float2*)&stage[rl * 66 + cl] =
                        make_float2(acc[m][j][rp * 2], acc[m][j][rp * 2 + 1]);
                }
    }
    __syncthreads();

    if (wn == 0) {
        const float* bb = bias_r + blockIdx.x * 128;
        const int hbase = blockIdx.x * 32;
#pragma unroll
        for (int m = 0; m < 2; m++)
#pragma unroll
            for (int j = 0; j < 4; j++)
#pragma unroll
                for (int rp = 0; rp < 2; rp++) {
                    const int rl = wm * 32 + m * 16 + (lane >> 2) + rp * 8;
                    const int hl = j * 8 + (lane & 3) * 2;
                    const int row = bm + rl;
                    const int hcol = hbase + hl;

                    const float iv0 = acc[m][j][rp * 2 + 0] + bb[hl];
                    const float iv1 = acc[m][j][rp * 2 + 1] + bb[hl + 1];
                    const float fv0 = acc[m][j + 4][rp * 2 + 0] + bb[32 + hl];
                    const float fv1 = acc[m][j + 4][rp * 2 + 1] + bb[32 + hl + 1];
                    const float gv0 = stage[rl * 66 + hl]          + bb[64 + hl];
                    const float gv1 = stage[rl * 66 + hl + 1]      + bb[64 + hl + 1];
                    const float ov0 = stage[rl * 66 + 32 + hl]     + bb[96 + hl];
                    const float ov1 = stage[rl * 66 + 32 + hl + 1] + bb[96 + hl + 1];

                    float2 cold = *(const float2*)&cst[(size_t)row * HD + hcol];
                    const float cn0 = sigf(fv0) * cold.x + sigf(iv0) * tanhf(gv0);
                    const float cn1 = sigf(fv1) * cold.y + sigf(iv1) * tanhf(gv1);
                    const float hn0 = sigf(ov0) * tanhf(cn0);
                    const float hn1 = sigf(ov1) * tanhf(cn1);

                    *(float2*)&cst[(size_t)row * HD + hcol]  = make_float2(cn0, cn1);
                    *(float2*)&Aout[(size_t)row * KP + hcol] = make_float2(hn0, hn1);
                }
    }
}

// ---------------------------------------------------------------------------
// Head kernel: p = A[B,512] @ W[16,512]^T + b  (A row stride lda)
// out = concat(softmax(p[:, :15]), sigmoid(p[:, 15]))
// Writes xnext (row stride ldx) and optionally y (fp32, ldy).
// ---------------------------------------------------------------------------
__global__ __launch_bounds__(512)
void head16_kernel(const float* __restrict__ A, int lda,
                   const float* __restrict__ W, const float* __restrict__ b,
                   float* __restrict__ xnext, int ldx,
                   float* __restrict__ y, int ldy) {
    __shared__ __align__(16) float Ws[16][512];
    const int tid = threadIdx.x;
#pragma unroll
    for (int i = 0; i < 4; i++) {
        const int idx = tid + i * 512;
        ((float4*)&Ws[0][0])[idx] = ((const float4*)W)[idx];
    }
    __syncthreads();

    const int warp = tid >> 5, lane = tid & 31;
    const int row = blockIdx.x * 16 + warp;

    float acc[16];
#pragma unroll
    for (int c = 0; c < 16; c++) acc[c] = 0.0f;

#pragma unroll
    for (int it = 0; it < 4; it++) {
        const int k = it * 128 + lane * 4;
        float4 hv = *(const float4*)(A + (size_t)row * lda + k);
#pragma unroll
        for (int c = 0; c < 16; c++) {
            float4 wv = *(const float4*)&Ws[c][k];
            acc[c] += hv.x * wv.x + hv.y * wv.y + hv.z * wv.z + hv.w * wv.w;
        }
    }
#pragma unroll
    for (int off = 16; off > 0; off >>= 1)
#pragma unroll
        for (int c = 0; c < 16; c++)
            acc[c] += __shfl_xor_sync(0xffffffffu, acc[c], off);

    if (lane == 0) {
        float p[16];
#pragma unroll
        for (int c = 0; c < 16; c++) p[c] = acc[c] + b[c];
        float m = p[0];
#pragma unroll
        for (int c = 1; c < 15; c++) m = fmaxf(m, p[c]);
        float e[15], s = 0.0f;
#pragma unroll
        for (int c = 0; c < 15; c++) { e[c] = expf(p[c] - m); s += e[c]; }
        const float inv = 1.0f / s;
        float o[16];
#pragma unroll
        for (int c = 0; c < 15; c++) o[c] = e[c] * inv;
        o[15] = 1.0f / (1.0f + expf(-p[15]));

        float4* dx = (float4*)(xnext + (size_t)row * ldx);
        dx[0] = make_float4(o[0], o[1], o[2], o[3]);
        dx[1] = make_float4(o[4], o[5], o[6], o[7]);
        dx[2] = make_float4(o[8], o[9], o[10], o[11]);
        dx[3] = make_float4(o[12], o[13], o[14], o[15]);
        if (y) {
            float4* dy = (float4*)(y + (size_t)row * ldy);
            dy[0] = make_float4(o[0], o[1], o[2], o[3]);
            dy[1] = make_float4(o[4], o[5], o[6], o[7]);
            dy[2] = make_float4(o[8], o[9], o[10], o[11]);
            dy[3] = make_float4(o[12], o[13], o[14], o[15]);
        }
    }
}

// ---------------------------------------------------------------------------
// Prep kernels
// ---------------------------------------------------------------------------
// Build permuted concat weight [2048, 544] (cols 528..543 zero) + permuted bias.
// n = hbIdx*128 + g*32 + hl maps to original row on = g*512 + hbIdx*32 + hl.
__global__ void build_wcat(const float* __restrict__ Whh, const float* __restrict__ Wih,
                           const float* __restrict__ bih, const float* __restrict__ bhh,
                           float* __restrict__ Wc, float* __restrict__ bias_r) {
    int idx = blockIdx.x * 256 + threadIdx.x;
    if (idx >= 2048 * KP) return;
    int n = idx / KP, k = idx % KP;
    int hbIdx = n >> 7, g = (n >> 5) & 3, hl = n & 31;
    int on = g * 512 + hbIdx * 32 + hl;
    float v = 0.0f;
    if (k < 512)      v = Whh[(size_t)on * 512 + k];
    else if (k < 528) v = Wih[(size_t)on * 16 + (k - 512)];
    Wc[idx] = v;
    if (k == 0) bias_r[n] = bih[on] + bhh[on];
}

// Zero the pad columns (528..543) of both Acat buffers.
__global__ void zero_pad_kernel(float* __restrict__ a0, float* __restrict__ a1) {
    int idx = blockIdx.x * 256 + threadIdx.x;   // over BB*16
    if (idx >= BB * 16) return;
    int row = idx >> 4, c = idx & 15;
    a0[(size_t)row * KP + 528 + c] = 0.0f;
    a1[(size_t)row * KP + 528 + c] = 0.0f;
}

// ---------------------------------------------------------------------------
// kernel_launch
// ---------------------------------------------------------------------------
extern "C" void kernel_launch(void* const* d_in, const int* in_sizes, int n_in,
                              void* d_out, int out_size) {
    const float* x   = (const float*)d_in[0];
    const float* W1  = (const float*)d_in[1];  const float* b1  = (const float*)d_in[2];
    const float* W2  = (const float*)d_in[3];  const float* b2  = (const float*)d_in[4];
    const float* W3  = (const float*)d_in[5];  const float* b3  = (const float*)d_in[6];
    const float* Wh1 = (const float*)d_in[7];  const float* bh1 = (const float*)d_in[8];
    const float* Wh2 = (const float*)d_in[9];  const float* bh2 = (const float*)d_in[10];
    const float* Wc1 = (const float*)d_in[11]; const float* bc1 = (const float*)d_in[12];
    const float* Wc2 = (const float*)d_in[13]; const float* bc2 = (const float*)d_in[14];
    const float* Wx1 = (const float*)d_in[15]; const float* bx1 = (const float*)d_in[16];
    const float* Wx2 = (const float*)d_in[17]; const float* bx2 = (const float*)d_in[18];
    const float* Wih = (const float*)d_in[19]; const float* bih = (const float*)d_in[20];
    const float* Whh = (const float*)d_in[21]; const float* bhh = (const float*)d_in[22];
    const float* Wp  = (const float*)d_in[23]; const float* bp  = (const float*)d_in[24];
    float* out = (float*)d_out;

    float *bufA, *bufB, *hx, *cbuf, *wcat, *biasr;
    cudaGetSymbolAddress((void**)&bufA, g_bufA);
    cudaGetSymbolAddress((void**)&bufB, g_bufB);
    cudaGetSymbolAddress((void**)&hx, g_hx);
    cudaGetSymbolAddress((void**)&cbuf, g_c);
    cudaGetSymbolAddress((void**)&wcat, g_Wcat);
    cudaGetSymbolAddress((void**)&biasr, g_biasr);

    float* a0 = hx;
    float* a1 = hx + (size_t)BB * KP;

    // Prep
    zero_pad_kernel<<<(BB * 16 + 255) / 256, 256>>>(a0, a1);
    build_wcat<<<(2048 * KP + 255) / 256, 256>>>(Whh, Wih, bih, bhh, wcat, biasr);

    const dim3 blk(256);
    const dim3 grd512(MLPD / 128, BB / 128);   // (4, 32)
    const dim3 grdL(HD / 32, BB / 128);        // (16, 32)

    // Prefix MLP (z ends in bufA)
    gemm_mma<1><<<grd512, blk>>>(x,    LATD, W1, LATD, b1, LATD, bufA, MLPD);
    gemm_mma<1><<<grd512, blk>>>(bufA, MLPD, W2, MLPD, b2, MLPD, bufB, MLPD);
    gemm_mma<1><<<grd512, blk>>>(bufB, MLPD, W3, MLPD, b3, MLPD, bufA, MLPD);
    // h0 -> a0 cols 0..511
    gemm_mma<1><<<grd512, blk>>>(bufA, MLPD, Wh1, MLPD, bh1, MLPD, bufB, MLPD);
    gemm_mma<0><<<grd512, blk>>>(bufB, MLPD, Wh2, MLPD, bh2, MLPD, a0, KP);
    // c0
    gemm_mma<1><<<grd512, blk>>>(bufA, MLPD, Wc1, MLPD, bc1, MLPD, bufB, MLPD);
    gemm_mma<0><<<grd512, blk>>>(bufB, MLPD, Wc2, MLPD, bc2, MLPD, cbuf, HD);
    // x0 -> a0 cols 512..527
    gemm_mma<1><<<grd512, blk>>>(bufA, MLPD, Wx1, MLPD, bx1, MLPD, bufB, MLPD);
    head16_kernel<<<BB / 16, 512>>>(bufB, MLPD, Wx2, bx2, a0 + 512, KP, nullptr, 0);

    // LSTM scan
    for (int t = 0; t < TT; t++) {
        float* ain  = (t & 1) ? a1 : a0;
        float* aout = (t & 1) ? a0 : a1;
        lstm_mma_kernel<<<grdL, blk>>>(ain, wcat, biasr, cbuf, aout);
        head16_kernel<<<BB / 16, 512>>>(aout, KP, Wp, bp, aout + 512, KP,
                                        out + t * IND, TT * IND);
    }
}

// round 8
// speedup vs baseline: 1.0011x; 1.0011x over previous
#include <cuda_runtime.h>
#include <math.h>
#include <stdint.h>

// Problem constants
#define BB   4096
#define LATD 128
#define HD   512
#define IND  16
#define TT   32
#define MLPD 512
#define KP   544   // 512 (h) + 16 (x) + 16 zero pad -> 17 * 32

// ---------------------------------------------------------------------------
// Scratch (static device globals; no runtime allocation allowed)
// ---------------------------------------------------------------------------
__device__ float g_bufA[BB * MLPD];
__device__ float g_bufB[BB * MLPD];
__device__ float g_hx[2][BB * KP];      // concat [h(512) | x(16) | pad(16)]
__device__ float g_c[BB * HD];
__device__ float g_Wcat[4 * HD * KP];   // permuted [2048, 544]
__device__ float g_biasr[4 * HD];       // permuted bih+bhh

__device__ __forceinline__ float sigf(float x) { return 1.0f / (1.0f + expf(-x)); }

// ---------------------------------------------------------------------------
// tf32 helpers
// ---------------------------------------------------------------------------
__device__ __forceinline__ void split_tf32(float v, uint32_t& hi, uint32_t& lo) {
    asm("cvt.rna.tf32.f32 %0, %1;" : "=r"(hi) : "f"(v));
    float r = v - __uint_as_float(hi);
    asm("cvt.rna.tf32.f32 %0, %1;" : "=r"(lo) : "f"(r));
}
__device__ __forceinline__ void mma_tf32(float* c, const uint32_t* a, const uint32_t* b) {
    asm volatile(
        "mma.sync.aligned.m16n8k8.row.col.f32.tf32.tf32.f32 "
        "{%0,%1,%2,%3}, {%4,%5,%6,%7}, {%8,%9}, {%0,%1,%2,%3};"
        : "+f"(c[0]), "+f"(c[1]), "+f"(c[2]), "+f"(c[3])
        : "r"(a[0]), "r"(a[1]), "r"(a[2]), "r"(a[3]), "r"(b[0]), "r"(b[1]));
}

#define SS 36   // smem row stride in floats (conflict-free fragment loads)

// ---------------------------------------------------------------------------
// Shared mainloop (3xTF32): acc[2][8][4] += A[bm:bm+128,:K] @ W[bn:bn+128,:K]^T
// A, W fp32 row-major (ld in floats). 256 threads = 8 warps, warp tile 32x64.
// K % 32 == 0. smem: sA[128][36], sW[128][36].
// ---------------------------------------------------------------------------
__device__ __forceinline__ void run_mainloop(
    float acc[2][8][4],
    const float* __restrict__ A, int lda,
    const float* __restrict__ W, int ldw,
    int K, int bm, int bn, float* smem)
{
    const int tid = threadIdx.x;
    const int wid = tid >> 5, lane = tid & 31;
    const int wm = wid >> 1, wn = wid & 1;
    const int g = lane >> 2, tig = lane & 3;

    float* sA = smem;
    float* sW = smem + 128 * SS;

    for (int k0 = 0; k0 < K; k0 += 32) {
#pragma unroll
        for (int p = 0; p < 4; p++) {
            const int lin = p * 1024 + tid * 4;
            const int r = lin >> 5, c = lin & 31;
            *(float4*)&sA[r * SS + c] = *(const float4*)&A[(size_t)(bm + r) * lda + k0 + c];
            *(float4*)&sW[r * SS + c] = *(const float4*)&W[(size_t)(bn + r) * ldw + k0 + c];
        }
        __syncthreads();

#pragma unroll
        for (int kk = 0; kk < 4; kk++) {
            const int kc = kk * 8 + tig;
            uint32_t aH[2][4], aL[2][4];
#pragma unroll
            for (int m = 0; m < 2; m++) {
                const int row = wm * 32 + m * 16 + g;
                split_tf32(sA[row * SS + kc],           aH[m][0], aL[m][0]);
                split_tf32(sA[(row + 8) * SS + kc],     aH[m][1], aL[m][1]);
                split_tf32(sA[row * SS + kc + 4],       aH[m][2], aL[m][2]);
                split_tf32(sA[(row + 8) * SS + kc + 4], aH[m][3], aL[m][3]);
            }
#pragma unroll
            for (int j = 0; j < 8; j++) {
                const int nrow = wn * 64 + j * 8 + g;
                uint32_t bH[2], bL[2];
                split_tf32(sW[nrow * SS + kc],     bH[0], bL[0]);
                split_tf32(sW[nrow * SS + kc + 4], bH[1], bL[1]);
#pragma unroll
                for (int m = 0; m < 2; m++) {
                    mma_tf32(acc[m][j], aH[m], bH);
                    mma_tf32(acc[m][j], aL[m], bH);
                    mma_tf32(acc[m][j], aH[m], bL);
                }
            }
        }
        __syncthreads();
    }
}

// ---------------------------------------------------------------------------
// GEMM: C[.,col] = act(A @ W^T + bias), fp32 out with row stride ldc.
// ACT: 0 none, 1 LeakyReLU(0.2). Grid: (N/128, M/128).
// ---------------------------------------------------------------------------
template <int ACT>
__global__ __launch_bounds__(256)
void gemm_mma(const float* __restrict__ A, int lda,
              const float* __restrict__ W, int ldw,
              const float* __restrict__ bias, int K,
              float* __restrict__ C, int ldc)
{
    __shared__ __align__(16) float smem[2 * 128 * SS];
    float acc[2][8][4] = {};
    const int bm = blockIdx.y * 128, bn = blockIdx.x * 128;

    run_mainloop(acc, A, lda, W, ldw, K, bm, bn, smem);

    const int wid = threadIdx.x >> 5, lane = threadIdx.x & 31;
    const int wm = wid >> 1, wn = wid & 1;

#pragma unroll
    for (int m = 0; m < 2; m++)
#pragma unroll
        for (int j = 0; j < 8; j++) {
            const int col = bn + wn * 64 + j * 8 + (lane & 3) * 2;
            const int row0 = bm + wm * 32 + m * 16 + (lane >> 2);
#pragma unroll
            for (int rp = 0; rp < 2; rp++) {
                const int r = row0 + rp * 8;
                float v0 = acc[m][j][rp * 2 + 0] + bias[col];
                float v1 = acc[m][j][rp * 2 + 1] + bias[col + 1];
                if (ACT == 1) {
                    v0 = (v0 >= 0.0f) ? v0 : 0.2f * v0;
                    v1 = (v1 >= 0.0f) ? v1 : 0.2f * v1;
                }
                *(float2*)&C[(size_t)r * ldc + col] = make_float2(v0, v1);
            }
        }
}

// ---------------------------------------------------------------------------
// LSTM fused gate kernel. A = [h|x|0] fp32 [B,544]; W = permuted [2048,544].
// CTA (nb, mb): rows mb*128, block-local cols: 0-31=i, 32-63=f, 64-95=g, 96-127=o
// for hcols nb*32..+31. Epilogue: g/o exchanged via smem, gate math, c updated
// in place, h written fp32 into next Acat buffer (cols 0..511, ld 544).
// ---------------------------------------------------------------------------
__global__ __launch_bounds__(256)
void lstm_mma_kernel(const float* __restrict__ Ain,
                     const float* __restrict__ W,
                     const float* __restrict__ bias_r,
                     float* __restrict__ cst,
                     float* __restrict__ Aout)
{
    __shared__ __align__(16) float smem[2 * 128 * SS];   // >= 128*66 floats
    float acc[2][8][4] = {};
    const int bm = blockIdx.y * 128, bn = blockIdx.x * 128;

    run_mainloop(acc, Ain, KP, W, KP, KP, bm, bn, smem);

    const int wid = threadIdx.x >> 5, lane = threadIdx.x & 31;
    const int wm = wid >> 1, wn = wid & 1;
    float* stage = smem;   // [128][66]

    if (wn == 1) {
#pragma unroll
        for (int m = 0; m < 2; m++)
#pragma unroll
            for (int j = 0; j < 8; j++)
#pragma unroll
                for (int rp = 0; rp < 2; rp++) {
                    const int rl = wm * 32 + m * 16 + (lane >> 2) + rp * 8;
                    const int cl = j * 8 + (lane & 3) * 2;
                    *(float2*)&stage[rl * 66 + cl] =
                        make_float2(acc[m][j][rp * 2], acc[m][j][rp * 2 + 1]);
                }
    }
    __syncthreads();

    if (wn == 0) {
        const float* bb = bias_r + blockIdx.x * 128;
        const int hbase = blockIdx.x * 32;
#pragma unroll
        for (int m = 0; m < 2; m++)
#pragma unroll
            for (int j = 0; j < 4; j++)
#pragma unroll
                for (int rp = 0; rp < 2; rp++) {
                    const int rl = wm * 32 + m * 16 + (lane >> 2) + rp * 8;
                    const int hl = j * 8 + (lane & 3) * 2;
                    const int row = bm + rl;
                    const int hcol = hbase + hl;

                    const float iv0 = acc[m][j][rp * 2 + 0] + bb[hl];
                    const float iv1 = acc[m][j][rp * 2 + 1] + bb[hl + 1];
                    const float fv0 = acc[m][j + 4][rp * 2 + 0] + bb[32 + hl];
                    const float fv1 = acc[m][j + 4][rp * 2 + 1] + bb[32 + hl + 1];
                    const float gv0 = stage[rl * 66 + hl]          + bb[64 + hl];
                    const float gv1 = stage[rl * 66 + hl + 1]      + bb[64 + hl + 1];
                    const float ov0 = stage[rl * 66 + 32 + hl]     + bb[96 + hl];
                    const float ov1 = stage[rl * 66 + 32 + hl + 1] + bb[96 + hl + 1];

                    float2 cold = *(const float2*)&cst[(size_t)row * HD + hcol];
                    const float cn0 = sigf(fv0) * cold.x + sigf(iv0) * tanhf(gv0);
                    const float cn1 = sigf(fv1) * cold.y + sigf(iv1) * tanhf(gv1);
                    const float hn0 = sigf(ov0) * tanhf(cn0);
                    const float hn1 = sigf(ov1) * tanhf(cn1);

                    *(float2*)&cst[(size_t)row * HD + hcol]  = make_float2(cn0, cn1);
                    *(float2*)&Aout[(size_t)row * KP + hcol] = make_float2(hn0, hn1);
                }
    }
}

// ---------------------------------------------------------------------------
// Head kernel: p = A[B,512] @ W[16,512]^T + b  (A row stride lda)
// out = concat(softmax(p[:, :15]), sigmoid(p[:, 15]))
// Writes xnext (row stride ldx) and optionally y (fp32, ldy).
// ---------------------------------------------------------------------------
__global__ __launch_bounds__(512)
void head16_kernel(const float* __restrict__ A, int lda,
                   const float* __restrict__ W, const float* __restrict__ b,
                   float* __restrict__ xnext, int ldx,
                   float* __restrict__ y, int ldy) {
    __shared__ __align__(16) float Ws[16][512];
    const int tid = threadIdx.x;
#pragma unroll
    for (int i = 0; i < 4; i++) {
        const int idx = tid + i * 512;
        ((float4*)&Ws[0][0])[idx] = ((const float4*)W)[idx];
    }
    __syncthreads();

    const int warp = tid >> 5, lane = tid & 31;
    const int row = blockIdx.x * 16 + warp;

    float acc[16];
#pragma unroll
    for (int c = 0; c < 16; c++) acc[c] = 0.0f;

#pragma unroll
    for (int it = 0; it < 4; it++) {
        const int k = it * 128 + lane * 4;
        float4 hv = *(const float4*)(A + (size_t)row * lda + k);
#pragma unroll
        for (int c = 0; c < 16; c++) {
            float4 wv = *(const float4*)&Ws[c][k];
            acc[c] += hv.x * wv.x + hv.y * wv.y + hv.z * wv.z + hv.w * wv.w;
        }
    }
#pragma unroll
    for (int off = 16; off > 0; off >>= 1)
#pragma unroll
        for (int c = 0; c < 16; c++)
            acc[c] += __shfl_xor_sync(0xffffffffu, acc[c], off);

    if (lane == 0) {
        float p[16];
#pragma unroll
        for (int c = 0; c < 16; c++) p[c] = acc[c] + b[c];
        float m = p[0];
#pragma unroll
        for (int c = 1; c < 15; c++) m = fmaxf(m, p[c]);
        float e[15], s = 0.0f;
#pragma unroll
        for (int c = 0; c < 15; c++) { e[c] = expf(p[c] - m); s += e[c]; }
        const float inv = 1.0f / s;
        float o[16];
#pragma unroll
        for (int c = 0; c < 15; c++) o[c] = e[c] * inv;
        o[15] = 1.0f / (1.0f + expf(-p[15]));

        float4* dx = (float4*)(xnext + (size_t)row * ldx);
        dx[0] = make_float4(o[0], o[1], o[2], o[3]);
        dx[1] = make_float4(o[4], o[5], o[6], o[7]);
        dx[2] = make_float4(o[8], o[9], o[10], o[11]);
        dx[3] = make_float4(o[12], o[13], o[14], o[15]);
        if (y) {
            float4* dy = (float4*)(y + (size_t)row * ldy);
            dy[0] = make_float4(o[0], o[1], o[2], o[3]);
            dy[1] = make_float4(o[4], o[5], o[6], o[7]);
            dy[2] = make_float4(o[8], o[9], o[10], o[11]);
            dy[3] = make_float4(o[12], o[13], o[14], o[15]);
        }
    }
}

// ---------------------------------------------------------------------------
// Prep kernels
// ---------------------------------------------------------------------------
// Build permuted concat weight [2048, 544] (cols 528..543 zero) + permuted bias.
// n = hbIdx*128 + g*32 + hl maps to original row on = g*512 + hbIdx*32 + hl.
__global__ void build_wcat(const float* __restrict__ Whh, const float* __restrict__ Wih,
                           const float* __restrict__ bih, const float* __restrict__ bhh,
                           float* __restrict__ Wc, float* __restrict__ bias_r) {
    int idx = blockIdx.x * 256 + threadIdx.x;
    if (idx >= 2048 * KP) return;
    int n = idx / KP, k = idx % KP;
    int hbIdx = n >> 7, g = (n >> 5) & 3, hl = n & 31;
    int on = g * 512 + hbIdx * 32 + hl;
    float v = 0.0f;
    if (k < 512)      v = Whh[(size_t)on * 512 + k];
    else if (k < 528) v = Wih[(size_t)on * 16 + (k - 512)];
    Wc[idx] = v;
    if (k == 0) bias_r[n] = bih[on] + bhh[on];
}

// Zero the pad columns (528..543) of both Acat buffers.
__global__ void zero_pad_kernel(float* __restrict__ a0, float* __restrict__ a1) {
    int idx = blockIdx.x * 256 + threadIdx.x;   // over BB*16
    if (idx >= BB * 16) return;
    int row = idx >> 4, c = idx & 15;
    a0[(size_t)row * KP + 528 + c] = 0.0f;
    a1[(size_t)row * KP + 528 + c] = 0.0f;
}

// ---------------------------------------------------------------------------
// kernel_launch
// ---------------------------------------------------------------------------
extern "C" void kernel_launch(void* const* d_in, const int* in_sizes, int n_in,
                              void* d_out, int out_size) {
    const float* x   = (const float*)d_in[0];
    const float* W1  = (const float*)d_in[1];  const float* b1  = (const float*)d_in[2];
    const float* W2  = (const float*)d_in[3];  const float* b2  = (const float*)d_in[4];
    const float* W3  = (const float*)d_in[5];  const float* b3  = (const float*)d_in[6];
    const float* Wh1 = (const float*)d_in[7];  const float* bh1 = (const float*)d_in[8];
    const float* Wh2 = (const float*)d_in[9];  const float* bh2 = (const float*)d_in[10];
    const float* Wc1 = (const float*)d_in[11]; const float* bc1 = (const float*)d_in[12];
    const float* Wc2 = (const float*)d_in[13]; const float* bc2 = (const float*)d_in[14];
    const float* Wx1 = (const float*)d_in[15]; const float* bx1 = (const float*)d_in[16];
    const float* Wx2 = (const float*)d_in[17]; const float* bx2 = (const float*)d_in[18];
    const float* Wih = (const float*)d_in[19]; const float* bih = (const float*)d_in[20];
    const float* Whh = (const float*)d_in[21]; const float* bhh = (const float*)d_in[22];
    const float* Wp  = (const float*)d_in[23]; const float* bp  = (const float*)d_in[24];
    float* out = (float*)d_out;

    float *bufA, *bufB, *hx, *cbuf, *wcat, *biasr;
    cudaGetSymbolAddress((void**)&bufA, g_bufA);
    cudaGetSymbolAddress((void**)&bufB, g_bufB);
    cudaGetSymbolAddress((void**)&hx, g_hx);
    cudaGetSymbolAddress((void**)&cbuf, g_c);
    cudaGetSymbolAddress((void**)&wcat, g_Wcat);
    cudaGetSymbolAddress((void**)&biasr, g_biasr);

    float* a0 = hx;
    float* a1 = hx + (size_t)BB * KP;

    // Prep
    zero_pad_kernel<<<(BB * 16 + 255) / 256, 256>>>(a0, a1);
    build_wcat<<<(2048 * KP + 255) / 256, 256>>>(Whh, Wih, bih, bhh, wcat, biasr);

    const dim3 blk(256);
    const dim3 grd512(MLPD / 128, BB / 128);   // (4, 32)
    const dim3 grdL(HD / 32, BB / 128);        // (16, 32)

    // Prefix MLP (z ends in bufA)
    gemm_mma<1><<<grd512, blk>>>(x,    LATD, W1, LATD, b1, LATD, bufA, MLPD);
    gemm_mma<1><<<grd512, blk>>>(bufA, MLPD, W2, MLPD, b2, MLPD, bufB, MLPD);
    gemm_mma<1><<<grd512, blk>>>(bufB, MLPD, W3, MLPD, b3, MLPD, bufA, MLPD);
    // h0 -> a0 cols 0..511
    gemm_mma<1><<<grd512, blk>>>(bufA, MLPD, Wh1, MLPD, bh1, MLPD, bufB, MLPD);
    gemm_mma<0><<<grd512, blk>>>(bufB, MLPD, Wh2, MLPD, bh2, MLPD, a0, KP);
    // c0
    gemm_mma<1><<<grd512, blk>>>(bufA, MLPD, Wc1, MLPD, bc1, MLPD, bufB, MLPD);
    gemm_mma<0><<<grd512, blk>>>(bufB, MLPD, Wc2, MLPD, bc2, MLPD, cbuf, HD);
    // x0 -> a0 cols 512..527
    gemm_mma<1><<<grd512, blk>>>(bufA, MLPD, Wx1, MLPD, bx1, MLPD, bufB, MLPD);
    head16_kernel<<<BB / 16, 512>>>(bufB, MLPD, Wx2, bx2, a0 + 512, KP, nullptr, 0);

    // LSTM scan
    for (int t = 0; t < TT; t++) {
        float* ain  = (t & 1) ? a1 : a0;
        float* aout = (t & 1) ? a0 : a1;
        lstm_mma_kernel<<<grdL, blk>>>(ain, wcat, biasr, cbuf, aout);
        head16_kernel<<<BB / 16, 512>>>(aout, KP, Wp, bp, aout + 512, KP,
                                        out + t * IND, TT * IND);
    }
}